// round 2
// baseline (speedup 1.0000x reference)
#include <cuda_runtime.h>

#define BATCH   256
#define SDIM    1024
#define TOT     4096
#define INDIM   2048
#define NCLS    1000
#define O_OFF   3072   // S + I

// scratch (device globals: no allocation allowed in kernel_launch)
__device__ float g_HA[BATCH * TOT];
__device__ float g_HB[BATCH * TOT];
__device__ float g_E [BATCH * SDIM];

// packed fp32x2 FMA (Blackwell FFMA2 — ptxas will not auto-generate this)
__device__ __forceinline__ float2 ffma2(float2 a, float2 b, float2 c) {
    float2 d;
    asm("fma.rn.f32x2 %0, %1, %2, %3;"
        : "=l"(*reinterpret_cast<unsigned long long*>(&d))
        : "l"(*reinterpret_cast<unsigned long long*>(&a)),
          "l"(*reinterpret_cast<unsigned long long*>(&b)),
          "l"(*reinterpret_cast<unsigned long long*>(&c)));
    return d;
}

// ---------------------------------------------------------------------------
// Step GEMM: Hn[256,4096] = relu(H[256,4096] @ W[4096,4096] (+ E on cols<1024))
// Tile 128x64, BK=32, 256 threads, double-buffered smem, reg prefetch.
// ---------------------------------------------------------------------------
#define AS_LD 132              // padded row length for As (4-way STS instead of 8)
#define BS_LD 64
#define AS_BUF (32 * AS_LD)    // floats per buffer
#define BS_BUF (32 * BS_LD)
#define SMEM_STEP ((2 * (AS_BUF + BS_BUF)) * (int)sizeof(float))

__global__ __launch_bounds__(256, 1)
void step_kernel(const float* __restrict__ H, const float* __restrict__ W,
                 const float* __restrict__ E, float* __restrict__ Hn, int addE)
{
    extern __shared__ float smem[];
    float* sA = smem;                 // [2][32][AS_LD], transposed: [k][row]
    float* sB = smem + 2 * AS_BUF;    // [2][32][BS_LD]: [k][col]

    const int tid = threadIdx.x;
    const int m_base = blockIdx.y * 128;
    const int n_base = blockIdx.x * 64;
    const int mt = (tid >> 4) * 8;    // 8 rows per thread
    const int nt = (tid & 15) * 4;    // 4 cols per thread

    float2 acc[4][4];
#pragma unroll
    for (int i = 0; i < 4; i++)
#pragma unroll
        for (int j = 0; j < 4; j++) acc[i][j] = make_float2(0.f, 0.f);

    // preload tile 0 into buffer 0
#pragma unroll
    for (int i = 0; i < 4; i++) {
        int idx = tid + i * 256;
        int row = idx >> 3, k4 = (idx & 7) * 4;
        float4 v = *(const float4*)&H[(m_base + row) * TOT + k4];
        sA[(k4 + 0) * AS_LD + row] = v.x;
        sA[(k4 + 1) * AS_LD + row] = v.y;
        sA[(k4 + 2) * AS_LD + row] = v.z;
        sA[(k4 + 3) * AS_LD + row] = v.w;
    }
#pragma unroll
    for (int i = 0; i < 2; i++) {
        int idx = tid + i * 256;
        int kr = idx >> 4, n4 = (idx & 15) * 4;
        *(float4*)&sB[kr * BS_LD + n4] = *(const float4*)&W[kr * TOT + n_base + n4];
    }
    __syncthreads();

    const int NTILE = TOT / 32;
    for (int kt = 0; kt < NTILE; kt++) {
        const float* As = sA + (kt & 1) * AS_BUF;
        const float* Bs = sB + (kt & 1) * BS_BUF;

        float4 pa[4]; float4 pb[2];
        if (kt + 1 < NTILE) {
            int k0 = (kt + 1) * 32;
#pragma unroll
            for (int i = 0; i < 4; i++) {
                int idx = tid + i * 256;
                int row = idx >> 3, k4 = (idx & 7) * 4;
                pa[i] = *(const float4*)&H[(m_base + row) * TOT + k0 + k4];
            }
#pragma unroll
            for (int i = 0; i < 2; i++) {
                int idx = tid + i * 256;
                int kr = idx >> 4, n4 = (idx & 15) * 4;
                pb[i] = *(const float4*)&W[(k0 + kr) * TOT + n_base + n4];
            }
        }

#pragma unroll
        for (int k = 0; k < 32; k++) {
            float4 a0 = *(const float4*)&As[k * AS_LD + mt];
            float4 a1 = *(const float4*)&As[k * AS_LD + mt + 4];
            float4 b  = *(const float4*)&Bs[k * BS_LD + nt];
            float2 A2[4] = { {a0.x, a0.y}, {a0.z, a0.w}, {a1.x, a1.y}, {a1.z, a1.w} };
            float2 B2[4] = { {b.x, b.x}, {b.y, b.y}, {b.z, b.z}, {b.w, b.w} };
#pragma unroll
            for (int i = 0; i < 4; i++)
#pragma unroll
                for (int j = 0; j < 4; j++)
                    acc[i][j] = ffma2(A2[i], B2[j], acc[i][j]);
        }

        if (kt + 1 < NTILE) {
            float* nA = sA + ((kt + 1) & 1) * AS_BUF;
            float* nB = sB + ((kt + 1) & 1) * BS_BUF;
#pragma unroll
            for (int i = 0; i < 4; i++) {
                int idx = tid + i * 256;
                int row = idx >> 3, k4 = (idx & 7) * 4;
                nA[(k4 + 0) * AS_LD + row] = pa[i].x;
                nA[(k4 + 1) * AS_LD + row] = pa[i].y;
                nA[(k4 + 2) * AS_LD + row] = pa[i].z;
                nA[(k4 + 3) * AS_LD + row] = pa[i].w;
            }
#pragma unroll
            for (int i = 0; i < 2; i++) {
                int idx = tid + i * 256;
                int kr = idx >> 4, n4 = (idx & 15) * 4;
                *(float4*)&nB[kr * BS_LD + n4] = pb[i];
            }
        }
        __syncthreads();
    }

    const bool doE = addE && (n_base < SDIM);
#pragma unroll
    for (int i = 0; i < 4; i++) {
#pragma unroll
        for (int half = 0; half < 2; half++) {
            int row = m_base + mt + 2 * i + half;
            int col = n_base + nt;
            float4 v;
            v.x = half ? acc[i][0].y : acc[i][0].x;
            v.y = half ? acc[i][1].y : acc[i][1].x;
            v.z = half ? acc[i][2].y : acc[i][2].x;
            v.w = half ? acc[i][3].y : acc[i][3].x;
            if (doE) {
                float4 e = *(const float4*)&E[row * SDIM + col];
                v.x += e.x; v.y += e.y; v.z += e.z; v.w += e.w;
            }
            v.x = fmaxf(v.x, 0.f); v.y = fmaxf(v.y, 0.f);
            v.z = fmaxf(v.z, 0.f); v.w = fmaxf(v.w, 0.f);
            *(float4*)&Hn[row * TOT + col] = v;
        }
    }
}

// ---------------------------------------------------------------------------
// NT GEMM with bias: C[256,N] = A[256,K](lda) @ Bt[N,K]^T + bias
// Used for E = x @ in_w^T + in_b and out = Os @ out_w^T + out_b.
// ---------------------------------------------------------------------------
__global__ __launch_bounds__(256, 1)
void gemm_nt_bias(const float* __restrict__ A, int lda,
                  const float* __restrict__ Bt, int N, int K, int ldc,
                  const float* __restrict__ bias, float* __restrict__ C)
{
    __shared__ float sA[32 * AS_LD];   // [k][row], transposed A tile 128x32
    __shared__ float sB[32 * 68];      // [k][n],   transposed Bt tile 64x32

    const int tid = threadIdx.x;
    const int m_base = blockIdx.y * 128;
    const int n_base = blockIdx.x * 64;
    const int mt = (tid >> 4) * 8;
    const int nt = (tid & 15) * 4;

    float2 acc[4][4];
#pragma unroll
    for (int i = 0; i < 4; i++)
#pragma unroll
        for (int j = 0; j < 4; j++) acc[i][j] = make_float2(0.f, 0.f);

    for (int k0 = 0; k0 < K; k0 += 32) {
#pragma unroll
        for (int i = 0; i < 4; i++) {
            int idx = tid + i * 256;
            int row = idx >> 3, k4 = (idx & 7) * 4;
            float4 v = *(const float4*)&A[(m_base + row) * lda + k0 + k4];
            sA[(k4 + 0) * AS_LD + row] = v.x;
            sA[(k4 + 1) * AS_LD + row] = v.y;
            sA[(k4 + 2) * AS_LD + row] = v.z;
            sA[(k4 + 3) * AS_LD + row] = v.w;
        }
#pragma unroll
        for (int i = 0; i < 2; i++) {
            int idx = tid + i * 256;
            int n = idx >> 3, k4 = (idx & 7) * 4;
            int gn = n_base + n;
            float4 v = make_float4(0.f, 0.f, 0.f, 0.f);
            if (gn < N) v = *(const float4*)&Bt[gn * K + k0 + k4];
            sB[(k4 + 0) * 68 + n] = v.x;
            sB[(k4 + 1) * 68 + n] = v.y;
            sB[(k4 + 2) * 68 + n] = v.z;
            sB[(k4 + 3) * 68 + n] = v.w;
        }
        __syncthreads();
#pragma unroll
        for (int k = 0; k < 32; k++) {
            float4 a0 = *(const float4*)&sA[k * AS_LD + mt];
            float4 a1 = *(const float4*)&sA[k * AS_LD + mt + 4];
            float4 b  = *(const float4*)&sB[k * 68 + nt];
            float2 A2[4] = { {a0.x, a0.y}, {a0.z, a0.w}, {a1.x, a1.y}, {a1.z, a1.w} };
            float2 B2[4] = { {b.x, b.x}, {b.y, b.y}, {b.z, b.z}, {b.w, b.w} };
#pragma unroll
            for (int i = 0; i < 4; i++)
#pragma unroll
                for (int j = 0; j < 4; j++)
                    acc[i][j] = ffma2(A2[i], B2[j], acc[i][j]);
        }
        __syncthreads();
    }

#pragma unroll
    for (int i = 0; i < 4; i++) {
#pragma unroll
        for (int half = 0; half < 2; half++) {
            int row = m_base + mt + 2 * i + half;
            float vals[4];
            vals[0] = half ? acc[i][0].y : acc[i][0].x;
            vals[1] = half ? acc[i][1].y : acc[i][1].x;
            vals[2] = half ? acc[i][2].y : acc[i][2].x;
            vals[3] = half ? acc[i][3].y : acc[i][3].x;
#pragma unroll
            for (int j = 0; j < 4; j++) {
                int col = n_base + nt + j;
                if (col < N) C[row * ldc + col] = vals[j] + bias[col];
            }
        }
    }
}

// H0: first 1024 cols = relu(E), rest = 0  (step t=0 with zero carry, gate=1)
__global__ __launch_bounds__(256)
void init_H(const float* __restrict__ E, float* __restrict__ H)
{
    int i = blockIdx.x * blockDim.x + threadIdx.x;       // over float4s
    int row = i / (TOT / 4);
    int c4  = (i % (TOT / 4)) * 4;
    float4 v = make_float4(0.f, 0.f, 0.f, 0.f);
    if (c4 < SDIM) {
        float4 e = *(const float4*)&E[row * SDIM + c4];
        v.x = fmaxf(e.x, 0.f); v.y = fmaxf(e.y, 0.f);
        v.z = fmaxf(e.z, 0.f); v.w = fmaxf(e.w, 0.f);
    }
    *(float4*)&H[row * TOT + c4] = v;
}

extern "C" void kernel_launch(void* const* d_in, const int* in_sizes, int n_in,
                              void* d_out, int out_size)
{
    const float* x     = (const float*)d_in[0];
    const float* W     = (const float*)d_in[1];
    const float* in_w  = (const float*)d_in[2];
    const float* in_b  = (const float*)d_in[3];
    const float* out_w = (const float*)d_in[4];
    const float* out_b = (const float*)d_in[5];
    float* out = (float*)d_out;

    float *HA, *HB, *E;
    cudaGetSymbolAddress((void**)&HA, g_HA);
    cudaGetSymbolAddress((void**)&HB, g_HB);
    cudaGetSymbolAddress((void**)&E,  g_E);
    cudaFuncSetAttribute(step_kernel, cudaFuncAttributeMaxDynamicSharedMemorySize, SMEM_STEP);

    dim3 blk(256);

    // E = x @ in_w^T + in_b           [256,1024]
    gemm_nt_bias<<<dim3(SDIM / 64, 2), blk>>>(x, INDIM, in_w, SDIM, INDIM, SDIM, in_b, E);

    // H1 = [relu(E), 0, 0]            (step t=0 folded)
    init_H<<<(BATCH * TOT / 4) / 256, blk>>>(E, HA);

    // steps t = 1..9 ; gate fires at t % 5 == 0 -> only t == 5
    float* cur = HA;
    float* nxt = HB;
    for (int t = 1; t < 10; t++) {
        step_kernel<<<dim3(TOT / 64, 2), blk, SMEM_STEP>>>(cur, W, E, nxt, (t % 5 == 0) ? 1 : 0);
        float* tmp = cur; cur = nxt; nxt = tmp;
    }

    // out = Os @ out_w^T + out_b ; Os = H[:, 3072:4096]
    gemm_nt_bias<<<dim3((NCLS + 63) / 64, 2), blk>>>(cur + O_OFF, TOT, out_w, NCLS, 1024, NCLS, out_b, out);
}

// round 5
// speedup vs baseline: 1.5787x; 1.5787x over previous
#include <cuda_runtime.h>
#include <cuda_bf16.h>
#include <cstdint>

#define BATCH   256
#define SDIM    1024
#define TOT     4096
#define INDIM   2048
#define NCLS    1000
#define O_OFF   3072

// ---------------------------------------------------------------------------
// scratch (device globals: no allocation allowed)
// ---------------------------------------------------------------------------
__device__ __align__(256) __nv_bfloat16 g_Wthi[TOT * TOT];   // W^T hi  [n][k]
__device__ __align__(256) __nv_bfloat16 g_Wtlo[TOT * TOT];   // W^T lo
__device__ __align__(256) __nv_bfloat16 g_HhiA[BATCH * TOT];
__device__ __align__(256) __nv_bfloat16 g_HloA[BATCH * TOT];
__device__ __align__(256) __nv_bfloat16 g_HhiB[BATCH * TOT];
__device__ __align__(256) __nv_bfloat16 g_HloB[BATCH * TOT];
__device__ __align__(256) float         g_Hf32[BATCH * TOT];
__device__ __align__(256) float         g_E   [BATCH * SDIM];

__device__ __forceinline__ uint32_t smem_u32(const void* p) {
    uint32_t a;
    asm("{ .reg .u64 t; cvta.to.shared.u64 t, %1; cvt.u32.u64 %0, t; }" : "=r"(a) : "l"(p));
    return a;
}

// ---------------------------------------------------------------------------
// Step GEMM on mma.sync (HMMA bf16, fp32 accum), 3-product hi/lo split.
//   C[128,64] per CTA;  C = H @ W  with  Wt[n][k] = W[k][n]
//   Hn = relu(C + gate*E), emitted as bf16 hi/lo (+ f32 for O block at t=9)
// ---------------------------------------------------------------------------
#define MTILE   128
#define NTILE   64
#define BK      32
#define KTILES  (TOT / BK)            // 128
#define STRIDE  80                    // bytes per smem row (64B data + 16B pad)
#define A_TILE_B (MTILE * STRIDE)     // 10240
#define B_TILE_B (NTILE * STRIDE)     // 5120
#define OFF_AHI  0
#define OFF_ALO  (A_TILE_B)
#define OFF_BHI  (2 * A_TILE_B)
#define OFF_BLO  (2 * A_TILE_B + B_TILE_B)
#define STAGE_B  (2 * A_TILE_B + 2 * B_TILE_B)   // 30720
#define NSTAGES  4
#define SMEM_DYN (NSTAGES * STAGE_B)             // 122880

#define CP16(so, gp) asm volatile("cp.async.cg.shared.global [%0], [%1], 16;" :: "r"(so), "l"(gp))
#define CP_COMMIT()  asm volatile("cp.async.commit_group;" ::: "memory")

#define LDSM_X4(r0, r1, r2, r3, a)                                             \
    asm volatile("ldmatrix.sync.aligned.m8n8.x4.shared.b16 {%0,%1,%2,%3}, [%4];" \
                 : "=r"(r0), "=r"(r1), "=r"(r2), "=r"(r3) : "r"(a))

#define MMA16816(c, a, b)                                                      \
    asm volatile("mma.sync.aligned.m16n8k16.row.col.f32.bf16.bf16.f32 "        \
                 "{%0,%1,%2,%3},{%4,%5,%6,%7},{%8,%9},{%0,%1,%2,%3};"          \
                 : "+f"((c)[0]), "+f"((c)[1]), "+f"((c)[2]), "+f"((c)[3])      \
                 : "r"((a)[0]), "r"((a)[1]), "r"((a)[2]), "r"((a)[3]),         \
                   "r"((b)[0]), "r"((b)[1]))

__device__ __forceinline__ void load_stage(
    uint32_t sbase, int stage,
    const __nv_bfloat16* __restrict__ Ahi, const __nv_bfloat16* __restrict__ Alo,
    const __nv_bfloat16* __restrict__ Bhi, const __nv_bfloat16* __restrict__ Blo,
    int m_base, int n_base, int k0, int tid)
{
    const uint32_t st = sbase + stage * STAGE_B;
    // A tiles: 128 rows x 4 chunks(16B) = 512 chunks; 2 per thread
#pragma unroll
    for (int i = 0; i < 2; i++) {
        int c = tid + i * 256;
        int row = c >> 2, ch = c & 3;
        uint32_t so = st + row * STRIDE + ch * 16;
        size_t gi = (size_t)(m_base + row) * TOT + k0 + ch * 8;
        CP16(so + OFF_AHI, Ahi + gi);
        CP16(so + OFF_ALO, Alo + gi);
    }
    // B tiles: 64 rows x 4 chunks = 256 chunks; 1 per thread
    {
        int row = tid >> 2, ch = tid & 3;
        uint32_t so = st + row * STRIDE + ch * 16;
        size_t gi = (size_t)(n_base + row) * TOT + k0 + ch * 8;
        CP16(so + OFF_BHI, Bhi + gi);
        CP16(so + OFF_BLO, Blo + gi);
    }
}

__global__ __launch_bounds__(256, 1)
void step_mma(const __nv_bfloat16* __restrict__ Ahi, const __nv_bfloat16* __restrict__ Alo,
              const __nv_bfloat16* __restrict__ Bhi, const __nv_bfloat16* __restrict__ Blo,
              const float* __restrict__ E,
              __nv_bfloat16* __restrict__ Ohi, __nv_bfloat16* __restrict__ Olo,
              float* __restrict__ Of32, int addE, int writeF32)
{
    extern __shared__ char smem[];
    const uint32_t sbase = smem_u32(smem);

    const int tid    = threadIdx.x;
    const int lane   = tid & 31;
    const int wid    = tid >> 5;
    const int warp_m = wid >> 2;        // 0..1  -> 64 rows each
    const int warp_n = wid & 3;         // 0..3  -> 16 cols each
    const int n_base = blockIdx.x * NTILE;
    const int m_base = blockIdx.y * MTILE;

    float acc[4][2][4];                 // [mf][nf][4]
#pragma unroll
    for (int i = 0; i < 4; i++)
#pragma unroll
        for (int j = 0; j < 2; j++)
#pragma unroll
            for (int e = 0; e < 4; e++) acc[i][j][e] = 0.f;

    // prologue: stages 0..2
#pragma unroll
    for (int s = 0; s < 3; s++) {
        load_stage(sbase, s, Ahi, Alo, Bhi, Blo, m_base, n_base, s * BK, tid);
        CP_COMMIT();
    }

    // per-warp ldmatrix lane addressing (row = lane%16, +16B for lane/16)
    const int lrow = lane & 15;
    const int lcol = (lane >> 4) * 16;

    for (int kt = 0; kt < KTILES; kt++) {
        if (kt < KTILES - 3) asm volatile("cp.async.wait_group 2;" ::: "memory");
        else                 asm volatile("cp.async.wait_group 0;" ::: "memory");
        __syncthreads();

        if (kt + 3 < KTILES) {
            load_stage(sbase, (kt + 3) & 3, Ahi, Alo, Bhi, Blo,
                       m_base, n_base, (kt + 3) * BK, tid);
            CP_COMMIT();
        }

        const uint32_t st = sbase + (kt & 3) * STAGE_B;
#pragma unroll
        for (int h = 0; h < 2; h++) {   // two k16 halves of BK=32
            // B fragments (n16 per warp): one x4 each for hi and lo
            uint32_t bh[2][2], bl[2][2];
            {
                uint32_t ab = st + OFF_BHI + (warp_n * 16 + lrow) * STRIDE + h * 32 + lcol;
                uint32_t r0, r1, r2, r3;
                LDSM_X4(r0, r1, r2, r3, ab);
                bh[0][0] = r0; bh[0][1] = r2; bh[1][0] = r1; bh[1][1] = r3;
                LDSM_X4(r0, r1, r2, r3, ab + (OFF_BLO - OFF_BHI));
                bl[0][0] = r0; bl[0][1] = r2; bl[1][0] = r1; bl[1][1] = r3;
            }
#pragma unroll
            for (int mf = 0; mf < 4; mf++) {
                uint32_t ah[4], al[4];
                uint32_t aa = st + OFF_AHI + (warp_m * 64 + mf * 16 + lrow) * STRIDE + h * 32 + lcol;
                LDSM_X4(ah[0], ah[1], ah[2], ah[3], aa);
                LDSM_X4(al[0], al[1], al[2], al[3], aa + (OFF_ALO - OFF_AHI));
#pragma unroll
                for (int nf = 0; nf < 2; nf++) {
                    MMA16816(acc[mf][nf], ah, bh[nf]);
                    MMA16816(acc[mf][nf], al, bh[nf]);
                    MMA16816(acc[mf][nf], ah, bl[nf]);
                }
            }
        }
    }

    // -------- epilogue: relu(+E), bf16 hi/lo split, direct global writes -----
    const int r0   = lane >> 2;
    const int colq = (lane & 3) * 2;
    const bool doE = addE && (n_base < SDIM);
    const bool doF = writeF32 && (n_base >= O_OFF);

#pragma unroll
    for (int mf = 0; mf < 4; mf++) {
#pragma unroll
        for (int nf = 0; nf < 2; nf++) {
            const int gn = n_base + warp_n * 16 + nf * 8 + colq;
#pragma unroll
            for (int half = 0; half < 2; half++) {
                const int gm = m_base + warp_m * 64 + mf * 16 + r0 + half * 8;
                float x = acc[mf][nf][half * 2 + 0];
                float y = acc[mf][nf][half * 2 + 1];
                if (doE) {
                    float2 e = *(const float2*)&E[(size_t)gm * SDIM + gn];
                    x += e.x; y += e.y;
                }
                x = fmaxf(x, 0.f); y = fmaxf(y, 0.f);
                const size_t gi = (size_t)gm * TOT + gn;
                __nv_bfloat16 hx = __float2bfloat16(x);
                __nv_bfloat16 hy = __float2bfloat16(y);
                __nv_bfloat16 lx = __float2bfloat16(x - __bfloat162float(hx));
                __nv_bfloat16 ly = __float2bfloat16(y - __bfloat162float(hy));
                __nv_bfloat162 hp{hx, hy}, lp{lx, ly};
                *(uint32_t*)&Ohi[gi] = *(uint32_t*)&hp;
                *(uint32_t*)&Olo[gi] = *(uint32_t*)&lp;
                if (doF) *(float2*)&Of32[gi] = make_float2(x, y);
            }
        }
    }
}

// ---------------------------------------------------------------------------
// one-time per launch: split W into bf16 hi/lo and transpose to [n][k]
// ---------------------------------------------------------------------------
__global__ __launch_bounds__(256)
void split_transpose_W(const float* __restrict__ W,
                       __nv_bfloat16* __restrict__ Thi, __nv_bfloat16* __restrict__ Tlo)
{
    __shared__ float t[32][33];
    const int nb = blockIdx.x * 32, kb = blockIdx.y * 32;
    const int tx = threadIdx.x & 31, ty = threadIdx.x >> 5;
#pragma unroll
    for (int r = 0; r < 4; r++) {
        int row = ty + r * 8;  // k-local
        t[row][tx] = W[(size_t)(kb + row) * TOT + nb + tx];
    }
    __syncthreads();
#pragma unroll
    for (int r = 0; r < 4; r++) {
        int row = ty + r * 8;  // n-local
        float v = t[tx][row];
        __nv_bfloat16 h = __float2bfloat16(v);
        size_t gi = (size_t)(nb + row) * TOT + kb + tx;
        Thi[gi] = h;
        Tlo[gi] = __float2bfloat16(v - __bfloat162float(h));
    }
}

// H1 = [relu(E), 0, 0] as bf16 hi/lo (step t=0 folded; gate fires at t=0)
__global__ __launch_bounds__(256)
void init_H0(const float* __restrict__ E,
             __nv_bfloat16* __restrict__ Hhi, __nv_bfloat16* __restrict__ Hlo)
{
    int i = blockIdx.x * blockDim.x + threadIdx.x;
    int row = i >> 12, col = i & (TOT - 1);
    float y = 0.f;
    if (col < SDIM) y = fmaxf(E[row * SDIM + col], 0.f);
    __nv_bfloat16 h = __float2bfloat16(y);
    Hhi[i] = h;
    Hlo[i] = __float2bfloat16(y - __bfloat162float(h));
}

// ---------------------------------------------------------------------------
// scalar NT GEMM + bias (E projection, classifier)
// ---------------------------------------------------------------------------
__device__ __forceinline__ float2 ffma2(float2 a, float2 b, float2 c) {
    float2 d;
    asm("fma.rn.f32x2 %0, %1, %2, %3;"
        : "=l"(*reinterpret_cast<unsigned long long*>(&d))
        : "l"(*reinterpret_cast<unsigned long long*>(&a)),
          "l"(*reinterpret_cast<unsigned long long*>(&b)),
          "l"(*reinterpret_cast<unsigned long long*>(&c)));
    return d;
}
#define AS_LD 132

__global__ __launch_bounds__(256, 1)
void gemm_nt_bias(const float* __restrict__ A, int lda,
                  const float* __restrict__ Bt, int N, int K, int ldc,
                  const float* __restrict__ bias, float* __restrict__ C)
{
    __shared__ float sA[32 * AS_LD];
    __shared__ float sB[32 * 68];

    const int tid = threadIdx.x;
    const int m_base = blockIdx.y * 128;
    const int n_base = blockIdx.x * 64;
    const int mt = (tid >> 4) * 8;
    const int nt = (tid & 15) * 4;

    float2 acc[4][4];
#pragma unroll
    for (int i = 0; i < 4; i++)
#pragma unroll
        for (int j = 0; j < 4; j++) acc[i][j] = make_float2(0.f, 0.f);

    for (int k0 = 0; k0 < K; k0 += 32) {
#pragma unroll
        for (int i = 0; i < 4; i++) {
            int idx = tid + i * 256;
            int row = idx >> 3, k4 = (idx & 7) * 4;
            float4 v = *(const float4*)&A[(size_t)(m_base + row) * lda + k0 + k4];
            sA[(k4 + 0) * AS_LD + row] = v.x;
            sA[(k4 + 1) * AS_LD + row] = v.y;
            sA[(k4 + 2) * AS_LD + row] = v.z;
            sA[(k4 + 3) * AS_LD + row] = v.w;
        }
#pragma unroll
        for (int i = 0; i < 2; i++) {
            int idx = tid + i * 256;
            int n = idx >> 3, k4 = (idx & 7) * 4;
            int gn = n_base + n;
            float4 v = make_float4(0.f, 0.f, 0.f, 0.f);
            if (gn < N) v = *(const float4*)&Bt[(size_t)gn * K + k0 + k4];
            sB[(k4 + 0) * 68 + n] = v.x;
            sB[(k4 + 1) * 68 + n] = v.y;
            sB[(k4 + 2) * 68 + n] = v.z;
            sB[(k4 + 3) * 68 + n] = v.w;
        }
        __syncthreads();
#pragma unroll
        for (int k = 0; k < 32; k++) {
            float4 a0 = *(const float4*)&sA[k * AS_LD + mt];
            float4 a1 = *(const float4*)&sA[k * AS_LD + mt + 4];
            float4 b  = *(const float4*)&sB[k * 68 + nt];
            float2 A2[4] = { {a0.x, a0.y}, {a0.z, a0.w}, {a1.x, a1.y}, {a1.z, a1.w} };
            float2 B2[4] = { {b.x, b.x}, {b.y, b.y}, {b.z, b.z}, {b.w, b.w} };
#pragma unroll
            for (int i = 0; i < 4; i++)
#pragma unroll
                for (int j = 0; j < 4; j++)
                    acc[i][j] = ffma2(A2[i], B2[j], acc[i][j]);
        }
        __syncthreads();
    }

#pragma unroll
    for (int i = 0; i < 4; i++) {
#pragma unroll
        for (int half = 0; half < 2; half++) {
            int row = m_base + mt + 2 * i + half;
            float vals[4];
            vals[0] = half ? acc[i][0].y : acc[i][0].x;
            vals[1] = half ? acc[i][1].y : acc[i][1].x;
            vals[2] = half ? acc[i][2].y : acc[i][2].x;
            vals[3] = half ? acc[i][3].y : acc[i][3].x;
#pragma unroll
            for (int j = 0; j < 4; j++) {
                int col = n_base + nt + j;
                if (col < N) C[(size_t)row * ldc + col] = vals[j] + bias[col];
            }
        }
    }
}

// ---------------------------------------------------------------------------
extern "C" void kernel_launch(void* const* d_in, const int* in_sizes, int n_in,
                              void* d_out, int out_size)
{
    const float* x     = (const float*)d_in[0];
    const float* W     = (const float*)d_in[1];
    const float* in_w  = (const float*)d_in[2];
    const float* in_b  = (const float*)d_in[3];
    const float* out_w = (const float*)d_in[4];
    const float* out_b = (const float*)d_in[5];
    float* out = (float*)d_out;

    __nv_bfloat16 *Wthi, *Wtlo, *HhiA, *HloA, *HhiB, *HloB;
    float *Hf32, *E;
    cudaGetSymbolAddress((void**)&Wthi, g_Wthi);
    cudaGetSymbolAddress((void**)&Wtlo, g_Wtlo);
    cudaGetSymbolAddress((void**)&HhiA, g_HhiA);
    cudaGetSymbolAddress((void**)&HloA, g_HloA);
    cudaGetSymbolAddress((void**)&HhiB, g_HhiB);
    cudaGetSymbolAddress((void**)&HloB, g_HloB);
    cudaGetSymbolAddress((void**)&Hf32, g_Hf32);
    cudaGetSymbolAddress((void**)&E,    g_E);

    cudaFuncSetAttribute(step_mma, cudaFuncAttributeMaxDynamicSharedMemorySize, SMEM_DYN);

    // W -> bf16 hi/lo transposed [n][k]
    split_transpose_W<<<dim3(TOT / 32, TOT / 32), 256>>>(W, Wthi, Wtlo);

    // E = x @ in_w^T + in_b
    gemm_nt_bias<<<dim3(SDIM / 64, 2), 256>>>(x, INDIM, in_w, SDIM, INDIM, SDIM, in_b, E);

    // H1 = [relu(E), 0, 0]
    init_H0<<<(BATCH * TOT) / 256, 256>>>(E, HhiA, HloA);

    // steps t = 1..9 (gate only at t == 5)
    __nv_bfloat16 *cHi = HhiA, *cLo = HloA, *nHi = HhiB, *nLo = HloB;
    for (int t = 1; t < 10; t++) {
        step_mma<<<dim3(TOT / NTILE, BATCH / MTILE), 256, SMEM_DYN>>>(
            cHi, cLo, Wthi, Wtlo, E, nHi, nLo, Hf32,
            (t % 5 == 0) ? 1 : 0, (t == 9) ? 1 : 0);
        __nv_bfloat16* t1 = cHi; cHi = nHi; nHi = t1;
        __nv_bfloat16* t2 = cLo; cLo = nLo; nLo = t2;
    }

    // out = Os @ out_w^T + out_b ; Os = Hf32[:, 3072:4096]
    gemm_nt_bias<<<dim3((NCLS + 63) / 64, 2), 256>>>(Hf32 + O_OFF, TOT, out_w, NCLS, 1024, NCLS, out_b, out);
}

// round 6
// speedup vs baseline: 1.6028x; 1.0152x over previous
#include <cuda_runtime.h>
#include <cuda_bf16.h>
#include <cstdint>

#define BATCH   256
#define SDIM    1024
#define TOT     4096
#define INDIM   2048
#define NCLS    1000
#define O_OFF   3072

// ---------------------------------------------------------------------------
// scratch (device globals: no allocation allowed)
// ---------------------------------------------------------------------------
__device__ __align__(256) __nv_bfloat16 g_Wthi[TOT * TOT];   // W^T hi  [n][k]
__device__ __align__(256) __nv_bfloat16 g_Wtlo[TOT * TOT];   // W^T lo
__device__ __align__(256) __nv_bfloat16 g_HhiA[BATCH * TOT];
__device__ __align__(256) __nv_bfloat16 g_HloA[BATCH * TOT];
__device__ __align__(256) __nv_bfloat16 g_HhiB[BATCH * TOT];
__device__ __align__(256) __nv_bfloat16 g_HloB[BATCH * TOT];
__device__ __align__(256) float         g_Hf32[BATCH * TOT];
__device__ __align__(256) float         g_E   [BATCH * SDIM];

__device__ __forceinline__ uint32_t smem_u32(const void* p) {
    uint32_t a;
    asm("{ .reg .u64 t; cvta.to.shared.u64 t, %1; cvt.u32.u64 %0, t; }" : "=r"(a) : "l"(p));
    return a;
}

// ---------------------------------------------------------------------------
// Step GEMM on mma.sync (HMMA bf16, fp32 accum), 3-product hi/lo split.
//   C[128,64] per CTA;  C = H @ W  with  Wt[n][k] = W[k][n]
//   Hn = relu(C + gate*E), emitted as bf16 hi/lo (+ f32 for O block at t=9)
// ---------------------------------------------------------------------------
#define MTILE   128
#define NTILE   64
#define BK      32
#define KTILES  (TOT / BK)            // 128
#define STRIDE  80                    // bytes per smem row (64B data + 16B pad)
#define A_TILE_B (MTILE * STRIDE)     // 10240
#define B_TILE_B (NTILE * STRIDE)     // 5120
#define OFF_AHI  0
#define OFF_ALO  (A_TILE_B)
#define OFF_BHI  (2 * A_TILE_B)
#define OFF_BLO  (2 * A_TILE_B + B_TILE_B)
#define STAGE_B  (2 * A_TILE_B + 2 * B_TILE_B)   // 30720
#define NSTAGES  4
#define SMEM_DYN (NSTAGES * STAGE_B)             // 122880

#define CP16(so, gp) asm volatile("cp.async.cg.shared.global [%0], [%1], 16;" :: "r"(so), "l"(gp))
#define CP_COMMIT()  asm volatile("cp.async.commit_group;" ::: "memory")

#define LDSM_X4(r0, r1, r2, r3, a)                                             \
    asm volatile("ldmatrix.sync.aligned.m8n8.x4.shared.b16 {%0,%1,%2,%3}, [%4];" \
                 : "=r"(r0), "=r"(r1), "=r"(r2), "=r"(r3) : "r"(a))

#define MMA16816(c, a, b)                                                      \
    asm volatile("mma.sync.aligned.m16n8k16.row.col.f32.bf16.bf16.f32 "        \
                 "{%0,%1,%2,%3},{%4,%5,%6,%7},{%8,%9},{%0,%1,%2,%3};"          \
                 : "+f"((c)[0]), "+f"((c)[1]), "+f"((c)[2]), "+f"((c)[3])      \
                 : "r"((a)[0]), "r"((a)[1]), "r"((a)[2]), "r"((a)[3]),         \
                   "r"((b)[0]), "r"((b)[1]))

__device__ __forceinline__ void load_stage(
    uint32_t sbase, int stage,
    const __nv_bfloat16* __restrict__ Ahi, const __nv_bfloat16* __restrict__ Alo,
    const __nv_bfloat16* __restrict__ Bhi, const __nv_bfloat16* __restrict__ Blo,
    int m_base, int n_base, int k0, int tid)
{
    const uint32_t st = sbase + stage * STAGE_B;
    // A tiles: 128 rows x 4 chunks(16B) = 512 chunks; 2 per thread
#pragma unroll
    for (int i = 0; i < 2; i++) {
        int c = tid + i * 256;
        int row = c >> 2, ch = c & 3;
        uint32_t so = st + row * STRIDE + ch * 16;
        size_t gi = (size_t)(m_base + row) * TOT + k0 + ch * 8;
        CP16(so + OFF_AHI, Ahi + gi);
        CP16(so + OFF_ALO, Alo + gi);
    }
    // B tiles: 64 rows x 4 chunks = 256 chunks; 1 per thread
    {
        int row = tid >> 2, ch = tid & 3;
        uint32_t so = st + row * STRIDE + ch * 16;
        size_t gi = (size_t)(n_base + row) * TOT + k0 + ch * 8;
        CP16(so + OFF_BHI, Bhi + gi);
        CP16(so + OFF_BLO, Blo + gi);
    }
}

__global__ __launch_bounds__(256, 1)
void step_mma(const __nv_bfloat16* __restrict__ Ahi, const __nv_bfloat16* __restrict__ Alo,
              const __nv_bfloat16* __restrict__ Bhi, const __nv_bfloat16* __restrict__ Blo,
              const float* __restrict__ E,
              __nv_bfloat16* __restrict__ Ohi, __nv_bfloat16* __restrict__ Olo,
              float* __restrict__ Of32, int addE, int writeF32)
{
    extern __shared__ char smem[];
    const uint32_t sbase = smem_u32(smem);

    const int tid    = threadIdx.x;
    const int lane   = tid & 31;
    const int wid    = tid >> 5;
    const int warp_m = wid >> 2;        // 0..1  -> 64 rows each
    const int warp_n = wid & 3;         // 0..3  -> 16 cols each
    const int n_base = blockIdx.x * NTILE;
    const int m_base = blockIdx.y * MTILE;

    float acc[4][2][4];                 // [mf][nf][4]
#pragma unroll
    for (int i = 0; i < 4; i++)
#pragma unroll
        for (int j = 0; j < 2; j++)
#pragma unroll
            for (int e = 0; e < 4; e++) acc[i][j][e] = 0.f;

    // prologue: stages 0..2
#pragma unroll
    for (int s = 0; s < 3; s++) {
        load_stage(sbase, s, Ahi, Alo, Bhi, Blo, m_base, n_base, s * BK, tid);
        CP_COMMIT();
    }

    // per-warp ldmatrix lane addressing (row = lane%16, +16B for lane/16)
    const int lrow = lane & 15;
    const int lcol = (lane >> 4) * 16;

    for (int kt = 0; kt < KTILES; kt++) {
        if (kt < KTILES - 3) asm volatile("cp.async.wait_group 2;" ::: "memory");
        else                 asm volatile("cp.async.wait_group 0;" ::: "memory");
        __syncthreads();

        if (kt + 3 < KTILES) {
            load_stage(sbase, (kt + 3) & 3, Ahi, Alo, Bhi, Blo,
                       m_base, n_base, (kt + 3) * BK, tid);
            CP_COMMIT();
        }

        const uint32_t st = sbase + (kt & 3) * STAGE_B;
#pragma unroll
        for (int h = 0; h < 2; h++) {   // two k16 halves of BK=32
            // ---- load ALL fragments first ----
            uint32_t bh[2][2], bl[2][2];
            {
                uint32_t ab = st + OFF_BHI + (warp_n * 16 + lrow) * STRIDE + h * 32 + lcol;
                uint32_t r0, r1, r2, r3;
                LDSM_X4(r0, r1, r2, r3, ab);
                bh[0][0] = r0; bh[0][1] = r2; bh[1][0] = r1; bh[1][1] = r3;
                LDSM_X4(r0, r1, r2, r3, ab + (OFF_BLO - OFF_BHI));
                bl[0][0] = r0; bl[0][1] = r2; bl[1][0] = r1; bl[1][1] = r3;
            }
            uint32_t ah[4][4], al[4][4];
#pragma unroll
            for (int mf = 0; mf < 4; mf++) {
                uint32_t aa = st + OFF_AHI + (warp_m * 64 + mf * 16 + lrow) * STRIDE + h * 32 + lcol;
                LDSM_X4(ah[mf][0], ah[mf][1], ah[mf][2], ah[mf][3], aa);
                LDSM_X4(al[mf][0], al[mf][1], al[mf][2], al[mf][3], aa + (OFF_ALO - OFF_AHI));
            }
            // ---- product-major MMA issue: same acc reused at distance 8 ----
#pragma unroll
            for (int mf = 0; mf < 4; mf++)
#pragma unroll
                for (int nf = 0; nf < 2; nf++)
                    MMA16816(acc[mf][nf], ah[mf], bh[nf]);
#pragma unroll
            for (int mf = 0; mf < 4; mf++)
#pragma unroll
                for (int nf = 0; nf < 2; nf++)
                    MMA16816(acc[mf][nf], al[mf], bh[nf]);
#pragma unroll
            for (int mf = 0; mf < 4; mf++)
#pragma unroll
                for (int nf = 0; nf < 2; nf++)
                    MMA16816(acc[mf][nf], ah[mf], bl[nf]);
        }
    }

    // -------- epilogue: relu(+E), bf16 hi/lo split, direct global writes -----
    const int r0   = lane >> 2;
    const int colq = (lane & 3) * 2;
    const bool doE = addE && (n_base < SDIM);
    const bool doF = writeF32 && (n_base >= O_OFF);

#pragma unroll
    for (int mf = 0; mf < 4; mf++) {
#pragma unroll
        for (int nf = 0; nf < 2; nf++) {
            const int gn = n_base + warp_n * 16 + nf * 8 + colq;
#pragma unroll
            for (int half = 0; half < 2; half++) {
                const int gm = m_base + warp_m * 64 + mf * 16 + r0 + half * 8;
                float x = acc[mf][nf][half * 2 + 0];
                float y = acc[mf][nf][half * 2 + 1];
                if (doE) {
                    float2 e = *(const float2*)&E[(size_t)gm * SDIM + gn];
                    x += e.x; y += e.y;
                }
                x = fmaxf(x, 0.f); y = fmaxf(y, 0.f);
                const size_t gi = (size_t)gm * TOT + gn;
                __nv_bfloat16 hx = __float2bfloat16(x);
                __nv_bfloat16 hy = __float2bfloat16(y);
                __nv_bfloat16 lx = __float2bfloat16(x - __bfloat162float(hx));
                __nv_bfloat16 ly = __float2bfloat16(y - __bfloat162float(hy));
                __nv_bfloat162 hp{hx, hy}, lp{lx, ly};
                *(uint32_t*)&Ohi[gi] = *(uint32_t*)&hp;
                *(uint32_t*)&Olo[gi] = *(uint32_t*)&lp;
                if (doF) *(float2*)&Of32[gi] = make_float2(x, y);
            }
        }
    }
}

// ---------------------------------------------------------------------------
// one-time per launch: split W into bf16 hi/lo and transpose to [n][k]
// ---------------------------------------------------------------------------
__global__ __launch_bounds__(256)
void split_transpose_W(const float* __restrict__ W,
                       __nv_bfloat16* __restrict__ Thi, __nv_bfloat16* __restrict__ Tlo)
{
    __shared__ float t[32][33];
    const int nb = blockIdx.x * 32, kb = blockIdx.y * 32;
    const int tx = threadIdx.x & 31, ty = threadIdx.x >> 5;
#pragma unroll
    for (int r = 0; r < 4; r++) {
        int row = ty + r * 8;  // k-local
        t[row][tx] = W[(size_t)(kb + row) * TOT + nb + tx];
    }
    __syncthreads();
#pragma unroll
    for (int r = 0; r < 4; r++) {
        int row = ty + r * 8;  // n-local
        float v = t[tx][row];
        __nv_bfloat16 h = __float2bfloat16(v);
        size_t gi = (size_t)(nb + row) * TOT + kb + tx;
        Thi[gi] = h;
        Tlo[gi] = __float2bfloat16(v - __bfloat162float(h));
    }
}

// H1 = [relu(E), 0, 0] as bf16 hi/lo (step t=0 folded; gate fires at t=0)
__global__ __launch_bounds__(256)
void init_H0(const float* __restrict__ E,
             __nv_bfloat16* __restrict__ Hhi, __nv_bfloat16* __restrict__ Hlo)
{
    int i = blockIdx.x * blockDim.x + threadIdx.x;
    int row = i >> 12, col = i & (TOT - 1);
    float y = 0.f;
    if (col < SDIM) y = fmaxf(E[row * SDIM + col], 0.f);
    __nv_bfloat16 h = __float2bfloat16(y);
    Hhi[i] = h;
    Hlo[i] = __float2bfloat16(y - __bfloat162float(h));
}

// ---------------------------------------------------------------------------
// scalar NT GEMM + bias (E projection, classifier)
// ---------------------------------------------------------------------------
__device__ __forceinline__ float2 ffma2(float2 a, float2 b, float2 c) {
    float2 d;
    asm("fma.rn.f32x2 %0, %1, %2, %3;"
        : "=l"(*reinterpret_cast<unsigned long long*>(&d))
        : "l"(*reinterpret_cast<unsigned long long*>(&a)),
          "l"(*reinterpret_cast<unsigned long long*>(&b)),
          "l"(*reinterpret_cast<unsigned long long*>(&c)));
    return d;
}
#define AS_LD 132

__global__ __launch_bounds__(256, 1)
void gemm_nt_bias(const float* __restrict__ A, int lda,
                  const float* __restrict__ Bt, int N, int K, int ldc,
                  const float* __restrict__ bias, float* __restrict__ C)
{
    __shared__ float sA[32 * AS_LD];
    __shared__ float sB[32 * 68];

    const int tid = threadIdx.x;
    const int m_base = blockIdx.y * 128;
    const int n_base = blockIdx.x * 64;
    const int mt = (tid >> 4) * 8;
    const int nt = (tid & 15) * 4;

    float2 acc[4][4];
#pragma unroll
    for (int i = 0; i < 4; i++)
#pragma unroll
        for (int j = 0; j < 4; j++) acc[i][j] = make_float2(0.f, 0.f);

    for (int k0 = 0; k0 < K; k0 += 32) {
#pragma unroll
        for (int i = 0; i < 4; i++) {
            int idx = tid + i * 256;
            int row = idx >> 3, k4 = (idx & 7) * 4;
            float4 v = *(const float4*)&A[(size_t)(m_base + row) * lda + k0 + k4];
            sA[(k4 + 0) * AS_LD + row] = v.x;
            sA[(k4 + 1) * AS_LD + row] = v.y;
            sA[(k4 + 2) * AS_LD + row] = v.z;
            sA[(k4 + 3) * AS_LD + row] = v.w;
        }
#pragma unroll
        for (int i = 0; i < 2; i++) {
            int idx = tid + i * 256;
            int n = idx >> 3, k4 = (idx & 7) * 4;
            int gn = n_base + n;
            float4 v = make_float4(0.f, 0.f, 0.f, 0.f);
            if (gn < N) v = *(const float4*)&Bt[(size_t)gn * K + k0 + k4];
            sB[(k4 + 0) * 68 + n] = v.x;
            sB[(k4 + 1) * 68 + n] = v.y;
            sB[(k4 + 2) * 68 + n] = v.z;
            sB[(k4 + 3) * 68 + n] = v.w;
        }
        __syncthreads();
#pragma unroll
        for (int k = 0; k < 32; k++) {
            float4 a0 = *(const float4*)&sA[k * AS_LD + mt];
            float4 a1 = *(const float4*)&sA[k * AS_LD + mt + 4];
            float4 b  = *(const float4*)&sB[k * 68 + nt];
            float2 A2[4] = { {a0.x, a0.y}, {a0.z, a0.w}, {a1.x, a1.y}, {a1.z, a1.w} };
            float2 B2[4] = { {b.x, b.x}, {b.y, b.y}, {b.z, b.z}, {b.w, b.w} };
#pragma unroll
            for (int i = 0; i < 4; i++)
#pragma unroll
                for (int j = 0; j < 4; j++)
                    acc[i][j] = ffma2(A2[i], B2[j], acc[i][j]);
        }
        __syncthreads();
    }

#pragma unroll
    for (int i = 0; i < 4; i++) {
#pragma unroll
        for (int half = 0; half < 2; half++) {
            int row = m_base + mt + 2 * i + half;
            float vals[4];
            vals[0] = half ? acc[i][0].y : acc[i][0].x;
            vals[1] = half ? acc[i][1].y : acc[i][1].x;
            vals[2] = half ? acc[i][2].y : acc[i][2].x;
            vals[3] = half ? acc[i][3].y : acc[i][3].x;
#pragma unroll
            for (int j = 0; j < 4; j++) {
                int col = n_base + nt + j;
                if (col < N) C[(size_t)row * ldc + col] = vals[j] + bias[col];
            }
        }
    }
}

// ---------------------------------------------------------------------------
extern "C" void kernel_launch(void* const* d_in, const int* in_sizes, int n_in,
                              void* d_out, int out_size)
{
    const float* x     = (const float*)d_in[0];
    const float* W     = (const float*)d_in[1];
    const float* in_w  = (const float*)d_in[2];
    const float* in_b  = (const float*)d_in[3];
    const float* out_w = (const float*)d_in[4];
    const float* out_b = (const float*)d_in[5];
    float* out = (float*)d_out;

    __nv_bfloat16 *Wthi, *Wtlo, *HhiA, *HloA, *HhiB, *HloB;
    float *Hf32, *E;
    cudaGetSymbolAddress((void**)&Wthi, g_Wthi);
    cudaGetSymbolAddress((void**)&Wtlo, g_Wtlo);
    cudaGetSymbolAddress((void**)&HhiA, g_HhiA);
    cudaGetSymbolAddress((void**)&HloA, g_HloA);
    cudaGetSymbolAddress((void**)&HhiB, g_HhiB);
    cudaGetSymbolAddress((void**)&HloB, g_HloB);
    cudaGetSymbolAddress((void**)&Hf32, g_Hf32);
    cudaGetSymbolAddress((void**)&E,    g_E);

    cudaFuncSetAttribute(step_mma, cudaFuncAttributeMaxDynamicSharedMemorySize, SMEM_DYN);

    // W -> bf16 hi/lo transposed [n][k]
    split_transpose_W<<<dim3(TOT / 32, TOT / 32), 256>>>(W, Wthi, Wtlo);

    // E = x @ in_w^T + in_b
    gemm_nt_bias<<<dim3(SDIM / 64, 2), 256>>>(x, INDIM, in_w, SDIM, INDIM, SDIM, in_b, E);

    // H1 = [relu(E), 0, 0]
    init_H0<<<(BATCH * TOT) / 256, 256>>>(E, HhiA, HloA);

    // steps t = 1..9 (gate only at t == 5)
    __nv_bfloat16 *cHi = HhiA, *cLo = HloA, *nHi = HhiB, *nLo = HloB;
    for (int t = 1; t < 10; t++) {
        step_mma<<<dim3(TOT / NTILE, BATCH / MTILE), 256, SMEM_DYN>>>(
            cHi, cLo, Wthi, Wtlo, E, nHi, nLo, Hf32,
            (t % 5 == 0) ? 1 : 0, (t == 9) ? 1 : 0);
        __nv_bfloat16* t1 = cHi; cHi = nHi; nHi = t1;
        __nv_bfloat16* t2 = cLo; cLo = nLo; nLo = t2;
    }

    // out = Os @ out_w^T + out_b ; Os = Hf32[:, 3072:4096]
    gemm_nt_bias<<<dim3((NCLS + 63) / 64, 2), 256>>>(Hf32 + O_OFF, TOT, out_w, NCLS, 1024, NCLS, out_b, out);
}

// round 7
// speedup vs baseline: 1.6676x; 1.0405x over previous
#include <cuda_runtime.h>
#include <cuda_bf16.h>
#include <cstdint>

#define BATCH   256
#define SDIM    1024
#define TOT     4096
#define INDIM   2048
#define NCLS    1000
#define O_OFF   3072

// ---------------------------------------------------------------------------
// scratch (device globals: no allocation allowed)
// ---------------------------------------------------------------------------
__device__ __align__(256) __nv_bfloat16 g_Wthi[TOT * TOT];   // W^T hi  [n][k]
__device__ __align__(256) __nv_bfloat16 g_Wtlo[TOT * TOT];   // W^T lo
__device__ __align__(256) __nv_bfloat16 g_HhiA[BATCH * TOT];
__device__ __align__(256) __nv_bfloat16 g_HloA[BATCH * TOT];
__device__ __align__(256) __nv_bfloat16 g_HhiB[BATCH * TOT];
__device__ __align__(256) __nv_bfloat16 g_HloB[BATCH * TOT];
__device__ __align__(256) float         g_Hf32[BATCH * TOT];
__device__ __align__(256) float         g_E   [BATCH * SDIM];

__device__ __forceinline__ uint32_t smem_u32(const void* p) {
    uint32_t a;
    asm("{ .reg .u64 t; cvta.to.shared.u64 t, %1; cvt.u32.u64 %0, t; }" : "=r"(a) : "l"(p));
    return a;
}

// ---------------------------------------------------------------------------
// Step GEMM on mma.sync (HMMA bf16, fp32 accum), 3-product hi/lo split.
//   C[128,64] per CTA, 512 threads / 16 warps, warp tile 16x32.
//   Hn = relu(C + gate*E), emitted as bf16 hi/lo (+ f32 for O block at t=9)
// ---------------------------------------------------------------------------
#define MTILE   128
#define NTILE   64
#define BK      32
#define KTILES  (TOT / BK)            // 128
#define STRIDE  80                    // bytes per smem row (64B data + 16B pad)
#define A_TILE_B (MTILE * STRIDE)     // 10240
#define B_TILE_B (NTILE * STRIDE)     // 5120
#define OFF_AHI  0
#define OFF_ALO  (A_TILE_B)
#define OFF_BHI  (2 * A_TILE_B)
#define OFF_BLO  (2 * A_TILE_B + B_TILE_B)
#define STAGE_B  (2 * A_TILE_B + 2 * B_TILE_B)   // 30720
#define NSTAGES  4
#define SMEM_DYN (NSTAGES * STAGE_B)             // 122880
#define NTHREADS 512

#define CP16(so, gp) asm volatile("cp.async.cg.shared.global [%0], [%1], 16;" :: "r"(so), "l"(gp))
#define CP_COMMIT()  asm volatile("cp.async.commit_group;" ::: "memory")

#define LDSM_X4(r0, r1, r2, r3, a)                                             \
    asm volatile("ldmatrix.sync.aligned.m8n8.x4.shared.b16 {%0,%1,%2,%3}, [%4];" \
                 : "=r"(r0), "=r"(r1), "=r"(r2), "=r"(r3) : "r"(a))

#define MMA16816(c, a, b)                                                      \
    asm volatile("mma.sync.aligned.m16n8k16.row.col.f32.bf16.bf16.f32 "        \
                 "{%0,%1,%2,%3},{%4,%5,%6,%7},{%8,%9},{%0,%1,%2,%3};"          \
                 : "+f"((c)[0]), "+f"((c)[1]), "+f"((c)[2]), "+f"((c)[3])      \
                 : "r"((a)[0]), "r"((a)[1]), "r"((a)[2]), "r"((a)[3]),         \
                   "r"((b)[0]), "r"((b)[1]))

__device__ __forceinline__ void load_stage(
    uint32_t sbase, int stage,
    const __nv_bfloat16* __restrict__ Ahi, const __nv_bfloat16* __restrict__ Alo,
    const __nv_bfloat16* __restrict__ Bhi, const __nv_bfloat16* __restrict__ Blo,
    int m_base, int n_base, int k0, int tid)
{
    const uint32_t st = sbase + stage * STAGE_B;
    // A tiles: 128 rows x 4 chunks(16B) = 512 chunks; 1 per thread (hi + lo)
    {
        int row = tid >> 2, ch = tid & 3;
        uint32_t so = st + row * STRIDE + ch * 16;
        size_t gi = (size_t)(m_base + row) * TOT + k0 + ch * 8;
        CP16(so + OFF_AHI, Ahi + gi);
        CP16(so + OFF_ALO, Alo + gi);
    }
    // B tiles: 64 rows x 4 chunks = 256 chunks; threads 0-255 hi, 256-511 lo
    {
        int c = tid & 255;
        int row = c >> 2, ch = c & 3;
        uint32_t so = st + row * STRIDE + ch * 16;
        size_t gi = (size_t)(n_base + row) * TOT + k0 + ch * 8;
        if (tid < 256) CP16(so + OFF_BHI, Bhi + gi);
        else           CP16(so + OFF_BLO, Blo + gi);
    }
}

__global__ __launch_bounds__(NTHREADS, 1)
void step_mma(const __nv_bfloat16* __restrict__ Ahi, const __nv_bfloat16* __restrict__ Alo,
              const __nv_bfloat16* __restrict__ Bhi, const __nv_bfloat16* __restrict__ Blo,
              const float* __restrict__ E,
              __nv_bfloat16* __restrict__ Ohi, __nv_bfloat16* __restrict__ Olo,
              float* __restrict__ Of32, int addE, int writeF32)
{
    extern __shared__ char smem[];
    const uint32_t sbase = smem_u32(smem);

    const int tid    = threadIdx.x;
    const int lane   = tid & 31;
    const int wid    = tid >> 5;        // 0..15
    const int warp_m = wid >> 1;        // 0..7  -> 16 rows each
    const int warp_n = wid & 1;         // 0..1  -> 32 cols each
    const int n_base = blockIdx.x * NTILE;
    const int m_base = blockIdx.y * MTILE;

    float acc[4][4];                    // [nf][4]
#pragma unroll
    for (int j = 0; j < 4; j++)
#pragma unroll
        for (int e = 0; e < 4; e++) acc[j][e] = 0.f;

    // prologue: stages 0..2
#pragma unroll
    for (int s = 0; s < 3; s++) {
        load_stage(sbase, s, Ahi, Alo, Bhi, Blo, m_base, n_base, s * BK, tid);
        CP_COMMIT();
    }

    // per-warp ldmatrix lane addressing (row = lane%16, +16B for lane/16)
    const int lrow = lane & 15;
    const int lcol = (lane >> 4) * 16;

    for (int kt = 0; kt < KTILES; kt++) {
        if (kt < KTILES - 3) asm volatile("cp.async.wait_group 2;" ::: "memory");
        else                 asm volatile("cp.async.wait_group 0;" ::: "memory");
        __syncthreads();

        if (kt + 3 < KTILES) {
            load_stage(sbase, (kt + 3) & 3, Ahi, Alo, Bhi, Blo,
                       m_base, n_base, (kt + 3) * BK, tid);
            CP_COMMIT();
        }

        const uint32_t st = sbase + (kt & 3) * STAGE_B;
#pragma unroll
        for (int h = 0; h < 2; h++) {   // two k16 halves of BK=32
            // ---- load all fragments ----
            uint32_t ah[4], al[4];
            {
                uint32_t aa = st + OFF_AHI + (warp_m * 16 + lrow) * STRIDE + h * 32 + lcol;
                LDSM_X4(ah[0], ah[1], ah[2], ah[3], aa);
                LDSM_X4(al[0], al[1], al[2], al[3], aa + (OFF_ALO - OFF_AHI));
            }
            uint32_t bh[4][2], bl[4][2];
#pragma unroll
            for (int p = 0; p < 2; p++) {
                uint32_t ab = st + OFF_BHI + (warp_n * 32 + p * 16 + lrow) * STRIDE + h * 32 + lcol;
                uint32_t r0, r1, r2, r3;
                LDSM_X4(r0, r1, r2, r3, ab);
                bh[p * 2 + 0][0] = r0; bh[p * 2 + 0][1] = r2;
                bh[p * 2 + 1][0] = r1; bh[p * 2 + 1][1] = r3;
                LDSM_X4(r0, r1, r2, r3, ab + (OFF_BLO - OFF_BHI));
                bl[p * 2 + 0][0] = r0; bl[p * 2 + 0][1] = r2;
                bl[p * 2 + 1][0] = r1; bl[p * 2 + 1][1] = r3;
            }
            // ---- product-major MMA issue ----
#pragma unroll
            for (int nf = 0; nf < 4; nf++)
                MMA16816(acc[nf], ah, bh[nf]);
#pragma unroll
            for (int nf = 0; nf < 4; nf++)
                MMA16816(acc[nf], al, bh[nf]);
#pragma unroll
            for (int nf = 0; nf < 4; nf++)
                MMA16816(acc[nf], ah, bl[nf]);
        }
    }

    // -------- epilogue: relu(+E), bf16 hi/lo split, direct global writes -----
    const int r0   = lane >> 2;
    const int colq = (lane & 3) * 2;
    const bool doE = addE && (n_base < SDIM);
    const bool doF = writeF32 && (n_base >= O_OFF);

#pragma unroll
    for (int nf = 0; nf < 4; nf++) {
        const int gn = n_base + warp_n * 32 + nf * 8 + colq;
#pragma unroll
        for (int half = 0; half < 2; half++) {
            const int gm = m_base + warp_m * 16 + r0 + half * 8;
            float x = acc[nf][half * 2 + 0];
            float y = acc[nf][half * 2 + 1];
            if (doE) {
                float2 e = *(const float2*)&E[(size_t)gm * SDIM + gn];
                x += e.x; y += e.y;
            }
            x = fmaxf(x, 0.f); y = fmaxf(y, 0.f);
            const size_t gi = (size_t)gm * TOT + gn;
            __nv_bfloat16 hx = __float2bfloat16(x);
            __nv_bfloat16 hy = __float2bfloat16(y);
            __nv_bfloat16 lx = __float2bfloat16(x - __bfloat162float(hx));
            __nv_bfloat16 ly = __float2bfloat16(y - __bfloat162float(hy));
            __nv_bfloat162 hp{hx, hy}, lp{lx, ly};
            *(uint32_t*)&Ohi[gi] = *(uint32_t*)&hp;
            *(uint32_t*)&Olo[gi] = *(uint32_t*)&lp;
            if (doF) *(float2*)&Of32[gi] = make_float2(x, y);
        }
    }
}

// ---------------------------------------------------------------------------
// one-time per launch: split W into bf16 hi/lo and transpose to [n][k]
// ---------------------------------------------------------------------------
__global__ __launch_bounds__(256)
void split_transpose_W(const float* __restrict__ W,
                       __nv_bfloat16* __restrict__ Thi, __nv_bfloat16* __restrict__ Tlo)
{
    __shared__ float t[32][33];
    const int nb = blockIdx.x * 32, kb = blockIdx.y * 32;
    const int tx = threadIdx.x & 31, ty = threadIdx.x >> 5;
#pragma unroll
    for (int r = 0; r < 4; r++) {
        int row = ty + r * 8;  // k-local
        t[row][tx] = W[(size_t)(kb + row) * TOT + nb + tx];
    }
    __syncthreads();
#pragma unroll
    for (int r = 0; r < 4; r++) {
        int row = ty + r * 8;  // n-local
        float v = t[tx][row];
        __nv_bfloat16 h = __float2bfloat16(v);
        size_t gi = (size_t)(nb + row) * TOT + kb + tx;
        Thi[gi] = h;
        Tlo[gi] = __float2bfloat16(v - __bfloat162float(h));
    }
}

// H1 = [relu(E), 0, 0] as bf16 hi/lo (step t=0 folded; gate fires at t=0)
__global__ __launch_bounds__(256)
void init_H0(const float* __restrict__ E,
             __nv_bfloat16* __restrict__ Hhi, __nv_bfloat16* __restrict__ Hlo)
{
    int i = blockIdx.x * blockDim.x + threadIdx.x;
    int row = i >> 12, col = i & (TOT - 1);
    float y = 0.f;
    if (col < SDIM) y = fmaxf(E[row * SDIM + col], 0.f);
    __nv_bfloat16 h = __float2bfloat16(y);
    Hhi[i] = h;
    Hlo[i] = __float2bfloat16(y - __bfloat162float(h));
}

// ---------------------------------------------------------------------------
// scalar NT GEMM + bias (E projection, classifier)
// ---------------------------------------------------------------------------
__device__ __forceinline__ float2 ffma2(float2 a, float2 b, float2 c) {
    float2 d;
    asm("fma.rn.f32x2 %0, %1, %2, %3;"
        : "=l"(*reinterpret_cast<unsigned long long*>(&d))
        : "l"(*reinterpret_cast<unsigned long long*>(&a)),
          "l"(*reinterpret_cast<unsigned long long*>(&b)),
          "l"(*reinterpret_cast<unsigned long long*>(&c)));
    return d;
}
#define AS_LD 132

__global__ __launch_bounds__(256, 1)
void gemm_nt_bias(const float* __restrict__ A, int lda,
                  const float* __restrict__ Bt, int N, int K, int ldc,
                  const float* __restrict__ bias, float* __restrict__ C)
{
    __shared__ float sA[32 * AS_LD];
    __shared__ float sB[32 * 68];

    const int tid = threadIdx.x;
    const int m_base = blockIdx.y * 128;
    const int n_base = blockIdx.x * 64;
    const int mt = (tid >> 4) * 8;
    const int nt = (tid & 15) * 4;

    float2 acc[4][4];
#pragma unroll
    for (int i = 0; i < 4; i++)
#pragma unroll
        for (int j = 0; j < 4; j++) acc[i][j] = make_float2(0.f, 0.f);

    for (int k0 = 0; k0 < K; k0 += 32) {
#pragma unroll
        for (int i = 0; i < 4; i++) {
            int idx = tid + i * 256;
            int row = idx >> 3, k4 = (idx & 7) * 4;
            float4 v = *(const float4*)&A[(size_t)(m_base + row) * lda + k0 + k4];
            sA[(k4 + 0) * AS_LD + row] = v.x;
            sA[(k4 + 1) * AS_LD + row] = v.y;
            sA[(k4 + 2) * AS_LD + row] = v.z;
            sA[(k4 + 3) * AS_LD + row] = v.w;
        }
#pragma unroll
        for (int i = 0; i < 2; i++) {
            int idx = tid + i * 256;
            int n = idx >> 3, k4 = (idx & 7) * 4;
            int gn = n_base + n;
            float4 v = make_float4(0.f, 0.f, 0.f, 0.f);
            if (gn < N) v = *(const float4*)&Bt[(size_t)gn * K + k0 + k4];
            sB[(k4 + 0) * 68 + n] = v.x;
            sB[(k4 + 1) * 68 + n] = v.y;
            sB[(k4 + 2) * 68 + n] = v.z;
            sB[(k4 + 3) * 68 + n] = v.w;
        }
        __syncthreads();
#pragma unroll
        for (int k = 0; k < 32; k++) {
            float4 a0 = *(const float4*)&sA[k * AS_LD + mt];
            float4 a1 = *(const float4*)&sA[k * AS_LD + mt + 4];
            float4 b  = *(const float4*)&sB[k * 68 + nt];
            float2 A2[4] = { {a0.x, a0.y}, {a0.z, a0.w}, {a1.x, a1.y}, {a1.z, a1.w} };
            float2 B2[4] = { {b.x, b.x}, {b.y, b.y}, {b.z, b.z}, {b.w, b.w} };
#pragma unroll
            for (int i = 0; i < 4; i++)
#pragma unroll
                for (int j = 0; j < 4; j++)
                    acc[i][j] = ffma2(A2[i], B2[j], acc[i][j]);
        }
        __syncthreads();
    }

#pragma unroll
    for (int i = 0; i < 4; i++) {
#pragma unroll
        for (int half = 0; half < 2; half++) {
            int row = m_base + mt + 2 * i + half;
            float vals[4];
            vals[0] = half ? acc[i][0].y : acc[i][0].x;
            vals[1] = half ? acc[i][1].y : acc[i][1].x;
            vals[2] = half ? acc[i][2].y : acc[i][2].x;
            vals[3] = half ? acc[i][3].y : acc[i][3].x;
#pragma unroll
            for (int j = 0; j < 4; j++) {
                int col = n_base + nt + j;
                if (col < N) C[(size_t)row * ldc + col] = vals[j] + bias[col];
            }
        }
    }
}

// ---------------------------------------------------------------------------
extern "C" void kernel_launch(void* const* d_in, const int* in_sizes, int n_in,
                              void* d_out, int out_size)
{
    const float* x     = (const float*)d_in[0];
    const float* W     = (const float*)d_in[1];
    const float* in_w  = (const float*)d_in[2];
    const float* in_b  = (const float*)d_in[3];
    const float* out_w = (const float*)d_in[4];
    const float* out_b = (const float*)d_in[5];
    float* out = (float*)d_out;

    __nv_bfloat16 *Wthi, *Wtlo, *HhiA, *HloA, *HhiB, *HloB;
    float *Hf32, *E;
    cudaGetSymbolAddress((void**)&Wthi, g_Wthi);
    cudaGetSymbolAddress((void**)&Wtlo, g_Wtlo);
    cudaGetSymbolAddress((void**)&HhiA, g_HhiA);
    cudaGetSymbolAddress((void**)&HloA, g_HloA);
    cudaGetSymbolAddress((void**)&HhiB, g_HhiB);
    cudaGetSymbolAddress((void**)&HloB, g_HloB);
    cudaGetSymbolAddress((void**)&Hf32, g_Hf32);
    cudaGetSymbolAddress((void**)&E,    g_E);

    cudaFuncSetAttribute(step_mma, cudaFuncAttributeMaxDynamicSharedMemorySize, SMEM_DYN);

    // W -> bf16 hi/lo transposed [n][k]
    split_transpose_W<<<dim3(TOT / 32, TOT / 32), 256>>>(W, Wthi, Wtlo);

    // E = x @ in_w^T + in_b
    gemm_nt_bias<<<dim3(SDIM / 64, 2), 256>>>(x, INDIM, in_w, SDIM, INDIM, SDIM, in_b, E);

    // H1 = [relu(E), 0, 0]
    init_H0<<<(BATCH * TOT) / 256, 256>>>(E, HhiA, HloA);

    // steps t = 1..9 (gate only at t == 5)
    __nv_bfloat16 *cHi = HhiA, *cLo = HloA, *nHi = HhiB, *nLo = HloB;
    for (int t = 1; t < 10; t++) {
        step_mma<<<dim3(TOT / NTILE, BATCH / MTILE), NTHREADS, SMEM_DYN>>>(
            cHi, cLo, Wthi, Wtlo, E, nHi, nLo, Hf32,
            (t % 5 == 0) ? 1 : 0, (t == 9) ? 1 : 0);
        __nv_bfloat16* t1 = cHi; cHi = nHi; nHi = t1;
        __nv_bfloat16* t2 = cLo; cLo = nLo; nLo = t2;
    }

    // out = Os @ out_w^T + out_b ; Os = Hf32[:, 3072:4096]
    gemm_nt_bias<<<dim3((NCLS + 63) / 64, 2), 256>>>(Hf32 + O_OFF, TOT, out_w, NCLS, 1024, NCLS, out_b, out);
}